// round 7
// baseline (speedup 1.0000x reference)
#include <cuda_runtime.h>
#include <math.h>

#define BATCH 4
#define SEQ   2048
#define DIM   1024
#define HDIM  64
#define NCHUNK 16
#define CHUNK  128          // SEQ / NCHUNK
#define MROWS  (BATCH * SEQ)   // 8192

// ---------------- scratch (static device globals; no allocation) ----------------
__device__ float g_ret  [(size_t)MROWS * DIM];
__device__ float g_inp  [(size_t)MROWS * DIM];
__device__ float g_gate [(size_t)MROWS * DIM];
__device__ float g_u    [(size_t)MROWS * DIM];
__device__ float g_p    [(size_t)MROWS * DIM];
__device__ float g_state[(size_t)MROWS * DIM];
__device__ float g_y    [(size_t)MROWS * DIM];   // y_t = gate_{t+1} * state_t

#define REC_CTAS 128
#define REC_COLS 8
#define FLAG_STRIDE 8                       // 32B spacing -> distinct L2 sectors
__device__ unsigned int g_flags[REC_CTAS * FLAG_STRIDE];

__device__ float g_E   [BATCH * NCHUNK * DIM];
__device__ float g_cin [BATCH * NCHUNK * DIM];

// ---------------- retention scan ----------------
__global__ void scan_pass1(const float* __restrict__ K, const float* __restrict__ V,
                           const float* __restrict__ decay)
{
    int d = blockIdx.x * 256 + threadIdx.x;
    int c = blockIdx.y;
    int b = blockIdx.z;
    float dec = decay[d >> 6];
    size_t base = ((size_t)b * SEQ + (size_t)c * CHUNK) * DIM + d;
    const float* kp = K + base;
    const float* vp = V + base;
    float r = 0.f;
#pragma unroll 8
    for (int i = 0; i < CHUNK; ++i) {
        r = dec * r + kp[(size_t)i * DIM] * vp[(size_t)i * DIM];
    }
    g_E[((size_t)b * NCHUNK + c) * DIM + d] = r;
}

__global__ void scan_pass2(const float* __restrict__ decay)
{
    int d = blockIdx.x * 256 + threadIdx.x;
    int b = blockIdx.y;
    float dec = decay[d >> 6];
    float decC = 1.f;
#pragma unroll
    for (int i = 0; i < CHUNK; ++i) decC *= dec;
    float carry = 0.f;
#pragma unroll
    for (int c = 0; c < NCHUNK; ++c) {
        size_t idx = ((size_t)b * NCHUNK + c) * DIM + d;
        g_cin[idx] = carry;
        carry = carry * decC + g_E[idx];
    }
}

__global__ void scan_pass3(const float* __restrict__ Q, const float* __restrict__ K,
                           const float* __restrict__ V, const float* __restrict__ decay)
{
    int d = blockIdx.x * 256 + threadIdx.x;
    int c = blockIdx.y;
    int b = blockIdx.z;
    float dec = decay[d >> 6];
    size_t base = ((size_t)b * SEQ + (size_t)c * CHUNK) * DIM + d;
    const float* qp = Q + base;
    const float* kp = K + base;
    const float* vp = V + base;
    float* rp = g_ret + base;
    float r = g_cin[((size_t)b * NCHUNK + c) * DIM + d];
#pragma unroll 8
    for (int i = 0; i < CHUNK; ++i) {
        r = dec * r + kp[(size_t)i * DIM] * vp[(size_t)i * DIM];
        rp[(size_t)i * DIM] = qp[(size_t)i * DIM] * r;
    }
}

// ---------------- SGEMM: C[m,n] = sum_k A[m*K+k] * B[n*K+k] (+epilogue) ----------------
// mode 0: C = acc + bias
// mode 1: gate: g = sigmoid(acc+bias); C = g; auxOut = (1-g) * auxIn
// mode 2: C += acc
// mode 3: C = acc
__global__ __launch_bounds__(256, 2)
void sgemm_nt(int M, int N, int Kd,
              const float* __restrict__ Am, const float* __restrict__ Bmat,
              const float* __restrict__ bias, float* __restrict__ C,
              const float* __restrict__ auxIn, float* __restrict__ auxOut, int mode)
{
    const int BM = 128, BN = 128, BK = 8, TM = 8, TN = 8;
    __shared__ float As[2][BK][BM];
    __shared__ float Bs[2][BK][BN];

    const int tid = threadIdx.x;
    const int mTile = blockIdx.y * BM;
    const int nTile = blockIdx.x * BN;
    const int lr = tid >> 1;
    const int lc = (tid & 1) * 4;
    const float* Ap = Am   + (size_t)(mTile + lr) * Kd + lc;
    const float* Bp = Bmat + (size_t)(nTile + lr) * Kd + lc;
    const int tr = (tid >> 4) * TM;
    const int tc = (tid & 15) * TN;

    float acc[TM][TN];
#pragma unroll
    for (int i = 0; i < TM; ++i)
#pragma unroll
        for (int j = 0; j < TN; ++j) acc[i][j] = 0.f;

    float4 a4 = *(const float4*)Ap;
    float4 b4 = *(const float4*)Bp;
    As[0][lc + 0][lr] = a4.x; As[0][lc + 1][lr] = a4.y;
    As[0][lc + 2][lr] = a4.z; As[0][lc + 3][lr] = a4.w;
    Bs[0][lc + 0][lr] = b4.x; Bs[0][lc + 1][lr] = b4.y;
    Bs[0][lc + 2][lr] = b4.z; Bs[0][lc + 3][lr] = b4.w;
    __syncthreads();

    int buf = 0;
    for (int kt = BK; kt <= Kd; kt += BK) {
        float4 na, nb;
        const bool more = (kt < Kd);
        if (more) {
            na = *(const float4*)(Ap + kt);
            nb = *(const float4*)(Bp + kt);
        }
#pragma unroll
        for (int kk = 0; kk < BK; ++kk) {
            float ra[TM], rb[TN];
            *(float4*)(ra)     = *(const float4*)&As[buf][kk][tr];
            *(float4*)(ra + 4) = *(const float4*)&As[buf][kk][tr + 4];
            *(float4*)(rb)     = *(const float4*)&Bs[buf][kk][tc];
            *(float4*)(rb + 4) = *(const float4*)&Bs[buf][kk][tc + 4];
#pragma unroll
            for (int i = 0; i < TM; ++i)
#pragma unroll
                for (int j = 0; j < TN; ++j)
                    acc[i][j] = fmaf(ra[i], rb[j], acc[i][j]);
        }
        if (more) {
            int nbuf = buf ^ 1;
            As[nbuf][lc + 0][lr] = na.x; As[nbuf][lc + 1][lr] = na.y;
            As[nbuf][lc + 2][lr] = na.z; As[nbuf][lc + 3][lr] = na.w;
            Bs[nbuf][lc + 0][lr] = nb.x; Bs[nbuf][lc + 1][lr] = nb.y;
            Bs[nbuf][lc + 2][lr] = nb.z; Bs[nbuf][lc + 3][lr] = nb.w;
            __syncthreads();
            buf = nbuf;
        }
    }

    float bv[TN];
    if (mode == 0 || mode == 1) {
#pragma unroll
        for (int j = 0; j < TN; ++j) bv[j] = bias[nTile + tc + j];
    }

#pragma unroll
    for (int i = 0; i < TM; ++i) {
        size_t row = (size_t)(mTile + tr + i);
        float* cp = C + row * N + nTile + tc;
        if (mode == 0) {
#pragma unroll
            for (int j = 0; j < TN; j += 4) {
                float4 v = make_float4(acc[i][j] + bv[j], acc[i][j + 1] + bv[j + 1],
                                       acc[i][j + 2] + bv[j + 2], acc[i][j + 3] + bv[j + 3]);
                *(float4*)(cp + j) = v;
            }
        } else if (mode == 3) {
#pragma unroll
            for (int j = 0; j < TN; j += 4) {
                float4 v = make_float4(acc[i][j], acc[i][j + 1], acc[i][j + 2], acc[i][j + 3]);
                *(float4*)(cp + j) = v;
            }
        } else if (mode == 2) {
#pragma unroll
            for (int j = 0; j < TN; j += 4) {
                float4 prev = *(const float4*)(cp + j);
                prev.x += acc[i][j];     prev.y += acc[i][j + 1];
                prev.z += acc[i][j + 2]; prev.w += acc[i][j + 3];
                *(float4*)(cp + j) = prev;
            }
        } else { // gate
            const float* ip = auxIn + row * N + nTile + tc;
            float* up = auxOut + row * N + nTile + tc;
#pragma unroll
            for (int j = 0; j < TN; ++j) {
                float g = 1.f / (1.f + __expf(-(acc[i][j] + bv[j])));
                cp[j] = g;
                up[j] = (1.f - g) * ip[j];
            }
        }
    }
}

// ---------------- persistent state recurrence (v7) ----------------
// state_t = tanh( y_{t-1} @ A^T + P_t ),  y_t = gate_{t+1} (*) state_t  (producer-folded)
// 128 co-resident CTAs, 8 output columns each.
// v7 = v5 (proven) + (a) A slice in registers (plain float4, no packing),
//      (b) poller (warp 0) decoupled from finisher (warp 1) so the t+1 poll
//          overlaps the t finish, and the post-publish barrier is dropped.
// Sync protocol identical to v5: per-thread threadfence in finisher, then
// one volatile flag store; consumers volatile-poll flags.
__global__ __launch_bounds__(256, 1)
void recurrence_kernel(const float* __restrict__ gate, const float* __restrict__ P,
                       const float* __restrict__ Amat, float* __restrict__ state)
{
    __shared__ float xs[BATCH * DIM];       // y_{t-1} staged
    __shared__ float red[8 * 16];           // per-warp partials

    const int tid = threadIdx.x;
    const int warp = tid >> 5, lane = tid & 31;
    const int col0 = blockIdx.x * REC_COLS;
    const int cg = warp & 1;      // column group (4 cols)
    const int ks = warp >> 1;     // k slice (256 floats each)

    // ---- A slice in registers (loop-invariant): 8 float4 = 32 regs ----
    float4 aA[2][4];
#pragma unroll
    for (int i = 0; i < 2; ++i) {
        int k4 = ks * 64 + i * 32 + lane;       // float4 index in [0,256)
#pragma unroll
        for (int c = 0; c < 4; ++c)
            aA[i][c] = ((const float4*)(Amat + (size_t)(col0 + cg * 4 + c) * DIM))[k4];
    }

    // finisher = warp 1 (tid 32..63): output coordinates
    const int f = tid - 32;
    const int f_cg = (f >> 4) & 1, f_bb = (f >> 2) & 3, f_c = f & 3;
    const int f_col = col0 + f_cg * 4 + f_c;
    const bool is_fin = (warp == 1);

    // staging coordinates (4 float4 per thread)
    int pbb[4], pk4[4];
#pragma unroll
    for (int j = 0; j < 4; ++j) {
        int idx = tid + j * 256;
        pbb[j] = idx >> 8;
        pk4[j] = idx & 255;
    }

    __syncthreads();

    for (int t = 0; t < SEQ; ++t) {
        // ---- (A) finisher prefetches P_t and gate_{t+1} (barrier-independent) ----
        float pval = 0.f, gval = 0.f;
        if (is_fin) {
            pval = P[((size_t)f_bb * SEQ + t) * DIM + f_col];
            if (t + 1 < SEQ)
                gval = gate[((size_t)f_bb * SEQ + (t + 1)) * DIM + f_col];
        }

        // ---- (B) warp 0 polls: all CTAs have published y_{t-1} ----
        if (t > 0 && warp == 0) {
            unsigned tgt = (unsigned)t;
            bool ok;
            do {
                bool good = true;
#pragma unroll
                for (int j = 0; j < 4; ++j) {
                    unsigned fl = *(volatile const unsigned*)
                        &g_flags[(lane + 32 * j) * FLAG_STRIDE];
                    good = good && (fl >= tgt);
                }
                ok = __all_sync(0xffffffffu, good);
            } while (!ok);
        }
        __syncthreads();

        // ---- (C) stage y_{t-1} into SMEM ----
        if (t == 0) {
#pragma unroll
            for (int j = 0; j < 4; ++j)
                ((float4*)(xs + pbb[j] * DIM))[pk4[j]] = make_float4(0.f, 0.f, 0.f, 0.f);
        } else {
#pragma unroll
            for (int j = 0; j < 4; ++j) {
                float4 y4 = __ldcg(&((const float4*)(g_y + ((size_t)pbb[j] * SEQ + t - 1) * DIM))[pk4[j]]);
                ((float4*)(xs + pbb[j] * DIM))[pk4[j]] = y4;
            }
        }
        __syncthreads();

        // ---- (D) partial dots: 4 batches x 4 cols over 256-float k slice ----
        float acc[4][4];
#pragma unroll
        for (int bb = 0; bb < 4; ++bb)
#pragma unroll
            for (int c = 0; c < 4; ++c) acc[bb][c] = 0.f;

#pragma unroll
        for (int i = 0; i < 2; ++i) {
            int k4 = ks * 64 + i * 32 + lane;
            float4 x4[4];
#pragma unroll
            for (int bb = 0; bb < 4; ++bb)
                x4[bb] = ((const float4*)(xs + bb * DIM))[k4];
#pragma unroll
            for (int c = 0; c < 4; ++c) {
                float4 a4 = aA[i][c];
#pragma unroll
                for (int bb = 0; bb < 4; ++bb) {
                    acc[bb][c] += x4[bb].x * a4.x + x4[bb].y * a4.y +
                                  x4[bb].z * a4.z + x4[bb].w * a4.w;
                }
            }
        }
#pragma unroll
        for (int bb = 0; bb < 4; ++bb)
#pragma unroll
            for (int c = 0; c < 4; ++c) {
                float v = acc[bb][c];
#pragma unroll
                for (int off = 16; off; off >>= 1)
                    v += __shfl_xor_sync(0xffffffffu, v, off);
                if (lane == 0) red[warp * 16 + bb * 4 + c] = v;
            }
        __syncthreads();

        // ---- (E) finisher warp: cross-warp sum, tanh, publish, flag ----
        if (is_fin) {
            float s = 0.f;
#pragma unroll
            for (int k = 0; k < 4; ++k)
                s += red[(k * 2 + f_cg) * 16 + f_bb * 4 + f_c];
            float sv = tanhf(s + pval);
            size_t idx = ((size_t)f_bb * SEQ + t) * DIM + f_col;
            __stcg(&state[idx], sv);
            if (t + 1 < SEQ)
                __stcg(&g_y[idx], sv * gval);
            __threadfence();          // order this thread's y/state stores (gpu scope)
            __syncwarp();             // all finisher lanes fenced
            if (f == 0)
                *(volatile unsigned*)&g_flags[blockIdx.x * FLAG_STRIDE] = (unsigned)(t + 1);
        }
        // No trailing __syncthreads: red is re-written only after the next
        // (C)->(D) barrier pair, which the finisher also passes; xs is not
        // read by the finisher path.
    }
}

__global__ void reset_flags()
{
    int i = threadIdx.x;
    if (i < REC_CTAS * FLAG_STRIDE) g_flags[i] = 0u;
}

// ---------------- launch ----------------
extern "C" void kernel_launch(void* const* d_in, const int* in_sizes, int n_in,
                              void* d_out, int out_size)
{
    const float* q     = (const float*)d_in[0];
    const float* k     = (const float*)d_in[1];
    const float* v     = (const float*)d_in[2];
    const float* Wi    = (const float*)d_in[3];
    const float* bi    = (const float*)d_in[4];
    const float* Wg    = (const float*)d_in[5];
    const float* bg    = (const float*)d_in[6];
    const float* A     = (const float*)d_in[7];
    const float* Bm    = (const float*)d_in[8];
    const float* Wo    = (const float*)d_in[9];
    const float* bo    = (const float*)d_in[10];
    const float* decay = (const float*)d_in[11];

    float *ret, *inp, *gate, *u, *p, *state;
    cudaGetSymbolAddress((void**)&ret,   g_ret);
    cudaGetSymbolAddress((void**)&inp,   g_inp);
    cudaGetSymbolAddress((void**)&gate,  g_gate);
    cudaGetSymbolAddress((void**)&u,     g_u);
    cudaGetSymbolAddress((void**)&p,     g_p);
    cudaGetSymbolAddress((void**)&state, g_state);

    dim3 sg(DIM / 256, NCHUNK, BATCH);
    scan_pass1<<<sg, 256>>>(k, v, decay);
    scan_pass2<<<dim3(DIM / 256, BATCH), 256>>>(decay);
    scan_pass3<<<sg, 256>>>(q, k, v, decay);

    dim3 gg(DIM / 128, MROWS / 128);
    // inp = ret @ Wi^T + bi
    sgemm_nt<<<gg, 256>>>(MROWS, DIM, DIM, ret, Wi, bi, inp, nullptr, nullptr, 0);
    // gate = sigmoid(inp @ Wg^T + bg); u = (1-gate) * inp
    sgemm_nt<<<gg, 256>>>(MROWS, DIM, DIM, inp, Wg, bg, gate, inp, u, 1);
    // p = u @ A^T
    sgemm_nt<<<gg, 256>>>(MROWS, DIM, DIM, u, A, nullptr, p, nullptr, nullptr, 3);
    // p += inp @ Bm^T
    sgemm_nt<<<gg, 256>>>(MROWS, DIM, DIM, inp, Bm, nullptr, p, nullptr, nullptr, 2);

    reset_flags<<<1, 1024>>>();
    recurrence_kernel<<<REC_CTAS, 256>>>(gate, p, A, state);

    // out = state @ Wo^T + bo
    sgemm_nt<<<gg, 256>>>(MROWS, DIM, DIM, state, Wo, bo, (float*)d_out,
                          nullptr, nullptr, 0);
}

// round 9
// speedup vs baseline: 1.4636x; 1.4636x over previous
#include <cuda_runtime.h>
#include <cuda_bf16.h>
#include <math.h>
#include <stdint.h>

#define BATCH 4
#define SEQ   2048
#define DIM   1024
#define NCHUNK 16
#define CHUNK  128          // SEQ / NCHUNK
#define MROWS  (BATCH * SEQ)   // 8192

// ---------------- scratch (static device globals; no allocation) ----------------
__device__ float g_ret  [(size_t)MROWS * DIM];
__device__ float g_inp  [(size_t)MROWS * DIM];
__device__ float g_gate [(size_t)MROWS * DIM];
__device__ float g_u    [(size_t)MROWS * DIM];
__device__ float g_p    [(size_t)MROWS * DIM];
__device__ float g_state[(size_t)MROWS * DIM];
__device__ float g_y    [(size_t)MROWS * DIM];   // y_t = gate_{t+1} * state_t

#define REC_CTAS 128
#define REC_COLS 8
#define FLAG_STRIDE 8
__device__ unsigned int g_flags[REC_CTAS * FLAG_STRIDE];

__device__ float g_E   [BATCH * NCHUNK * DIM];
__device__ float g_cin [BATCH * NCHUNK * DIM];

// ---------------- helpers ----------------
__device__ __forceinline__ uint32_t smem_u32(const void* p) {
    uint32_t a;
    asm("{ .reg .u64 t; cvta.to.shared.u64 t, %1; cvt.u32.u64 %0, t; }"
        : "=r"(a) : "l"(p));
    return a;
}
__device__ __forceinline__ void ldm4(uint32_t* r, uint32_t addr) {
    asm volatile("ldmatrix.sync.aligned.m8n8.x4.shared.b16 {%0,%1,%2,%3}, [%4];"
                 : "=r"(r[0]), "=r"(r[1]), "=r"(r[2]), "=r"(r[3]) : "r"(addr));
}
__device__ __forceinline__ void mma16816(float* d, const uint32_t* a, const uint32_t* b) {
    asm volatile("mma.sync.aligned.m16n8k16.row.col.f32.bf16.bf16.f32 "
                 "{%0,%1,%2,%3}, {%4,%5,%6,%7}, {%8,%9}, {%0,%1,%2,%3};"
                 : "+f"(d[0]), "+f"(d[1]), "+f"(d[2]), "+f"(d[3])
                 : "r"(a[0]), "r"(a[1]), "r"(a[2]), "r"(a[3]),
                   "r"(b[0]), "r"(b[1]));
}

// ---------------- retention scan ----------------
__global__ void scan_pass1(const float* __restrict__ K, const float* __restrict__ V,
                           const float* __restrict__ decay)
{
    int d = blockIdx.x * 256 + threadIdx.x;
    int c = blockIdx.y;
    int b = blockIdx.z;
    float dec = decay[d >> 6];
    size_t base = ((size_t)b * SEQ + (size_t)c * CHUNK) * DIM + d;
    const float* kp = K + base;
    const float* vp = V + base;
    float r = 0.f;
#pragma unroll 8
    for (int i = 0; i < CHUNK; ++i)
        r = dec * r + kp[(size_t)i * DIM] * vp[(size_t)i * DIM];
    g_E[((size_t)b * NCHUNK + c) * DIM + d] = r;
}

__global__ void scan_pass2(const float* __restrict__ decay)
{
    int d = blockIdx.x * 256 + threadIdx.x;
    int b = blockIdx.y;
    float dec = decay[d >> 6];
    float decC = 1.f;
#pragma unroll
    for (int i = 0; i < CHUNK; ++i) decC *= dec;
    float carry = 0.f;
#pragma unroll
    for (int c = 0; c < NCHUNK; ++c) {
        size_t idx = ((size_t)b * NCHUNK + c) * DIM + d;
        g_cin[idx] = carry;
        carry = carry * decC + g_E[idx];
    }
}

__global__ void scan_pass3(const float* __restrict__ Q, const float* __restrict__ K,
                           const float* __restrict__ V, const float* __restrict__ decay)
{
    int d = blockIdx.x * 256 + threadIdx.x;
    int c = blockIdx.y;
    int b = blockIdx.z;
    float dec = decay[d >> 6];
    size_t base = ((size_t)b * SEQ + (size_t)c * CHUNK) * DIM + d;
    const float* qp = Q + base;
    const float* kp = K + base;
    const float* vp = V + base;
    float* rp = g_ret + base;
    float r = g_cin[((size_t)b * NCHUNK + c) * DIM + d];
#pragma unroll 8
    for (int i = 0; i < CHUNK; ++i) {
        r = dec * r + kp[(size_t)i * DIM] * vp[(size_t)i * DIM];
        rp[(size_t)i * DIM] = qp[(size_t)i * DIM] * r;
    }
}

// ================= mma.sync split-bf16 GEMM =================
// C[m,n] = sum_k X[m,k] * W[n,k]  (+ optional X2,W2 accumulated on top)
// via D = Xhi*Whi + Xhi*Wlo + Xlo*Whi, fp32 register accumulators.
// Tile 128x128/CTA, BK=32, 8 warps (4m x 2n), warp tile 32x64.
// mode: 0 = C+bias; 1 = gate (sigmoid, aux); 3 = plain.
#define GM_LDS 40                       // padded row (elements): 80B stride

__device__ __forceinline__ void gm_load_tile(uint16_t* hiT, uint16_t* loT,
                                             const float* __restrict__ src,
                                             int rowBase, int kBase, int tid)
{
    const int row = tid >> 1;
    const int cb  = (tid & 1) * 16;
    const float4* sp = (const float4*)(src + (size_t)(rowBase + row) * DIM + kBase + cb);
    uint32_t* hp = (uint32_t*)hiT;
    uint32_t* lp = (uint32_t*)loT;
#pragma unroll
    for (int j = 0; j < 4; ++j) {
        float4 v = sp[j];
        uint32_t u0 = __float_as_uint(v.x), u1 = __float_as_uint(v.y);
        uint32_t u2 = __float_as_uint(v.z), u3 = __float_as_uint(v.w);
        uint32_t h01 = (u0 >> 16) | (u1 & 0xFFFF0000u);
        uint32_t h23 = (u2 >> 16) | (u3 & 0xFFFF0000u);
        float l0 = v.x - __uint_as_float(u0 & 0xFFFF0000u);
        float l1 = v.y - __uint_as_float(u1 & 0xFFFF0000u);
        float l2 = v.z - __uint_as_float(u2 & 0xFFFF0000u);
        float l3 = v.w - __uint_as_float(u3 & 0xFFFF0000u);
        uint32_t lo01, lo23;
        asm("cvt.rn.satfinite.bf16x2.f32 %0, %1, %2;" : "=r"(lo01) : "f"(l1), "f"(l0));
        asm("cvt.rn.satfinite.bf16x2.f32 %0, %1, %2;" : "=r"(lo23) : "f"(l3), "f"(l2));
        int e = row * GM_LDS + cb + j * 4;      // even
        hp[e >> 1]       = h01;
        hp[(e >> 1) + 1] = h23;
        lp[e >> 1]       = lo01;
        lp[(e >> 1) + 1] = lo23;
    }
}

__global__ __launch_bounds__(256)
void mma_gemm(const float* __restrict__ X1, const float* __restrict__ W1,
              const float* __restrict__ X2, const float* __restrict__ W2,
              const float* __restrict__ bias, float* __restrict__ C,
              const float* __restrict__ auxIn, float* __restrict__ auxOut,
              int mode, int dual)
{
    __shared__ __align__(16) uint16_t sAhi[128 * GM_LDS];
    __shared__ __align__(16) uint16_t sAlo[128 * GM_LDS];
    __shared__ __align__(16) uint16_t sBhi[128 * GM_LDS];
    __shared__ __align__(16) uint16_t sBlo[128 * GM_LDS];

    const int tid = threadIdx.x;
    const int wid = tid >> 5, lane = tid & 31;
    const int wm = wid >> 1;            // 0..3: 32-row band
    const int wn = wid & 1;             // 0..1: 64-col band
    const int nTile = blockIdx.x * 128;
    const int mTile = blockIdx.y * 128;

    float acc[2][8][4];
#pragma unroll
    for (int mt = 0; mt < 2; ++mt)
#pragma unroll
        for (int nt = 0; nt < 8; ++nt)
#pragma unroll
            for (int r = 0; r < 4; ++r) acc[mt][nt][r] = 0.f;

    // ldmatrix per-thread address components (element units)
    const uint32_t aRow  = wm * 32 + (lane & 15);
    const uint32_t aKoff = (lane >> 4) * 8;
    const uint32_t bRow  = wn * 64 + (lane & 7) + ((lane >> 4) << 3);
    const uint32_t bKoff = ((lane >> 3) & 1) * 8;
    const uint32_t bAhi = smem_u32(sAhi), bAlo = smem_u32(sAlo);
    const uint32_t bBhi = smem_u32(sBhi), bBlo = smem_u32(sBlo);

    const int nCh = dual ? 64 : 32;
    for (int c = 0; c < nCh; ++c) {
        const float* X = (c >= 32) ? X2 : X1;
        const float* W = (c >= 32) ? W2 : W1;
        const int kBase = (c & 31) * 32;

        gm_load_tile(sAhi, sAlo, X, mTile, kBase, tid);
        gm_load_tile(sBhi, sBlo, W, nTile, kBase, tid);
        __syncthreads();

#pragma unroll
        for (int kk = 0; kk < 2; ++kk) {
            uint32_t ahi[2][4], alo[2][4];
#pragma unroll
            for (int mt = 0; mt < 2; ++mt) {
                uint32_t off = 2u * ((aRow + mt * 16) * GM_LDS + kk * 16 + aKoff);
                ldm4(ahi[mt], bAhi + off);
                ldm4(alo[mt], bAlo + off);
            }
#pragma unroll
            for (int ng = 0; ng < 4; ++ng) {
                uint32_t bhi[4], blo[4];
                uint32_t off = 2u * ((bRow + ng * 16) * GM_LDS + kk * 16 + bKoff);
                ldm4(bhi, bBhi + off);
                ldm4(blo, bBlo + off);
#pragma unroll
                for (int mt = 0; mt < 2; ++mt)
#pragma unroll
                    for (int h = 0; h < 2; ++h) {
                        float* d = acc[mt][ng * 2 + h];
                        mma16816(d, ahi[mt], bhi + h * 2);
                        mma16816(d, ahi[mt], blo + h * 2);
                        mma16816(d, alo[mt], bhi + h * 2);
                    }
            }
        }
        __syncthreads();
    }

    // ---- epilogue from register accumulators ----
    const int g = lane >> 2, tig = lane & 3;
#pragma unroll
    for (int mt = 0; mt < 2; ++mt) {
#pragma unroll
        for (int nt = 0; nt < 8; ++nt) {
            const int col = nTile + wn * 64 + nt * 8 + tig * 2;
            const int r0 = mTile + wm * 32 + mt * 16 + g;
            const int r1 = r0 + 8;
            float* d = acc[mt][nt];
            if (mode == 0) {
                float2 bv = *(const float2*)(bias + col);
                *(float2*)(C + (size_t)r0 * DIM + col) =
                    make_float2(d[0] + bv.x, d[1] + bv.y);
                *(float2*)(C + (size_t)r1 * DIM + col) =
                    make_float2(d[2] + bv.x, d[3] + bv.y);
            } else if (mode == 1) {
                float2 bv = *(const float2*)(bias + col);
                float2 i0 = *(const float2*)(auxIn + (size_t)r0 * DIM + col);
                float2 i1 = *(const float2*)(auxIn + (size_t)r1 * DIM + col);
                float g0 = 1.f / (1.f + __expf(-(d[0] + bv.x)));
                float g1 = 1.f / (1.f + __expf(-(d[1] + bv.y)));
                float g2 = 1.f / (1.f + __expf(-(d[2] + bv.x)));
                float g3 = 1.f / (1.f + __expf(-(d[3] + bv.y)));
                *(float2*)(C + (size_t)r0 * DIM + col) = make_float2(g0, g1);
                *(float2*)(C + (size_t)r1 * DIM + col) = make_float2(g2, g3);
                *(float2*)(auxOut + (size_t)r0 * DIM + col) =
                    make_float2((1.f - g0) * i0.x, (1.f - g1) * i0.y);
                *(float2*)(auxOut + (size_t)r1 * DIM + col) =
                    make_float2((1.f - g2) * i1.x, (1.f - g3) * i1.y);
            } else {
                *(float2*)(C + (size_t)r0 * DIM + col) = make_float2(d[0], d[1]);
                *(float2*)(C + (size_t)r1 * DIM + col) = make_float2(d[2], d[3]);
            }
        }
    }
}

// ================= persistent state recurrence (v5 — proven @7877) =================
#define REC_SMEM ((REC_COLS * DIM + BATCH * DIM + 8 * 16) * 4)

__global__ __launch_bounds__(256, 1)
void recurrence_kernel(const float* __restrict__ gate, const float* __restrict__ P,
                       const float* __restrict__ Amat, float* __restrict__ state)
{
    extern __shared__ float sh[];
    float* Asub = sh;
    float* xs   = sh + REC_COLS * DIM;
    float* red  = xs + BATCH * DIM;

    const int tid = threadIdx.x;
    const int warp = tid >> 5, lane = tid & 31;
    const int col0 = blockIdx.x * REC_COLS;
    const int cg = warp & 1;
    const int ks = warp >> 1;

    for (int i = tid; i < REC_COLS * DIM / 4; i += 256) {
        int c = i >> 8, k4 = i & 255;
        ((float4*)(Asub + c * DIM))[k4] =
            ((const float4*)(Amat + (size_t)(col0 + c) * DIM))[k4];
    }

    const int f_cg = tid >> 4, f_bb = (tid >> 2) & 3, f_c = tid & 3;
    const int f_col = col0 + f_cg * 4 + f_c;

    int pbb[4], pk4[4];
#pragma unroll
    for (int j = 0; j < 4; ++j) {
        int idx = tid + j * 256;
        pbb[j] = idx >> 8;
        pk4[j] = idx & 255;
    }

    __syncthreads();

    for (int t = 0; t < SEQ; ++t) {
        float pval = 0.f, gval = 0.f;
        if (tid < 32) {
            pval = P[((size_t)f_bb * SEQ + t) * DIM + f_col];
            if (t + 1 < SEQ)
                gval = gate[((size_t)f_bb * SEQ + (t + 1)) * DIM + f_col];
        }

        if (t > 0 && warp == 0) {
            unsigned tgt = (unsigned)t;
            bool ok;
            do {
                bool good = true;
#pragma unroll
                for (int j = 0; j < 4; ++j) {
                    unsigned f = *(volatile const unsigned*)
                        &g_flags[(lane + 32 * j) * FLAG_STRIDE];
                    good = good && (f >= tgt);
                }
                ok = __all_sync(0xffffffffu, good);
            } while (!ok);
        }
        __syncthreads();

        if (t == 0) {
#pragma unroll
            for (int j = 0; j < 4; ++j)
                ((float4*)(xs + pbb[j] * DIM))[pk4[j]] = make_float4(0.f, 0.f, 0.f, 0.f);
        } else {
#pragma unroll
            for (int j = 0; j < 4; ++j) {
                float4 y4 = __ldcg(&((const float4*)(g_y + ((size_t)pbb[j] * SEQ + t - 1) * DIM))[pk4[j]]);
                ((float4*)(xs + pbb[j] * DIM))[pk4[j]] = y4;
            }
        }
        __syncthreads();

        float acc[4][4];
#pragma unroll
        for (int bb = 0; bb < 4; ++bb)
#pragma unroll
            for (int c = 0; c < 4; ++c) acc[bb][c] = 0.f;

#pragma unroll
        for (int i = 0; i < 2; ++i) {
            int k4 = ks * 64 + i * 32 + lane;
            float4 x4[4];
#pragma unroll
            for (int bb = 0; bb < 4; ++bb)
                x4[bb] = ((const float4*)(xs + bb * DIM))[k4];
#pragma unroll
            for (int c = 0; c < 4; ++c) {
                float4 a4 = ((const float4*)(Asub + (cg * 4 + c) * DIM))[k4];
#pragma unroll
                for (int bb = 0; bb < 4; ++bb) {
                    acc[bb][c] += x4[bb].x * a4.x + x4[bb].y * a4.y +
                                  x4[bb].z * a4.z + x4[bb].w * a4.w;
                }
            }
        }
#pragma unroll
        for (int bb = 0; bb < 4; ++bb)
#pragma unroll
            for (int c = 0; c < 4; ++c) {
                float v = acc[bb][c];
#pragma unroll
                for (int off = 16; off; off >>= 1)
                    v += __shfl_xor_sync(0xffffffffu, v, off);
                acc[bb][c] = v;
            }
        if (lane == 0) {
#pragma unroll
            for (int bb = 0; bb < 4; ++bb)
#pragma unroll
                for (int c = 0; c < 4; ++c)
                    red[warp * 16 + bb * 4 + c] = acc[bb][c];
        }
        __syncthreads();

        if (tid < 32) {
            float s = 0.f;
#pragma unroll
            for (int k = 0; k < 4; ++k)
                s += red[(k * 2 + f_cg) * 16 + f_bb * 4 + f_c];
            float sv = tanhf(s + pval);
            size_t idx = ((size_t)f_bb * SEQ + t) * DIM + f_col;
            __stcg(&state[idx], sv);
            if (t + 1 < SEQ)
                __stcg(&g_y[idx], sv * gval);
            __threadfence();
        }
        __syncthreads();

        if (tid == 0)
            *(volatile unsigned*)&g_flags[blockIdx.x * FLAG_STRIDE] = (unsigned)(t + 1);
        __syncthreads();
    }
}

__global__ void reset_flags()
{
    int i = threadIdx.x;
    if (i < REC_CTAS * FLAG_STRIDE) g_flags[i] = 0u;
}

// ================= launch =================
extern "C" void kernel_launch(void* const* d_in, const int* in_sizes, int n_in,
                              void* d_out, int out_size)
{
    const float* q     = (const float*)d_in[0];
    const float* k     = (const float*)d_in[1];
    const float* v     = (const float*)d_in[2];
    const float* Wi    = (const float*)d_in[3];
    const float* bi    = (const float*)d_in[4];
    const float* Wg    = (const float*)d_in[5];
    const float* bg    = (const float*)d_in[6];
    const float* A     = (const float*)d_in[7];
    const float* Bm    = (const float*)d_in[8];
    const float* Wo    = (const float*)d_in[9];
    const float* bo    = (const float*)d_in[10];
    const float* decay = (const float*)d_in[11];

    float *ret, *inp, *gate, *u, *p, *state;
    cudaGetSymbolAddress((void**)&ret,   g_ret);
    cudaGetSymbolAddress((void**)&inp,   g_inp);
    cudaGetSymbolAddress((void**)&gate,  g_gate);
    cudaGetSymbolAddress((void**)&u,     g_u);
    cudaGetSymbolAddress((void**)&p,     g_p);
    cudaGetSymbolAddress((void**)&state, g_state);

    cudaFuncSetAttribute(recurrence_kernel,
                         cudaFuncAttributeMaxDynamicSharedMemorySize, REC_SMEM);

    dim3 sg(DIM / 256, NCHUNK, BATCH);
    scan_pass1<<<sg, 256>>>(k, v, decay);
    scan_pass2<<<dim3(DIM / 256, BATCH), 256>>>(decay);
    scan_pass3<<<sg, 256>>>(q, k, v, decay);

    dim3 gg(DIM / 128, MROWS / 128);   // (8, 64)
    // inp = ret @ Wi^T + bi
    mma_gemm<<<gg, 256>>>(ret, Wi, nullptr, nullptr, bi, inp,
                          nullptr, nullptr, 0, 0);
    // gate = sigmoid(inp @ Wg^T + bg); u = (1-gate) * inp
    mma_gemm<<<gg, 256>>>(inp, Wg, nullptr, nullptr, bg, gate,
                          inp, u, 1, 0);
    // p = u @ A^T + inp @ Bm^T   (fused dual accumulation)
    mma_gemm<<<gg, 256>>>(u, A, inp, Bm, nullptr, p,
                          nullptr, nullptr, 3, 1);

    reset_flags<<<1, 1024>>>();
    recurrence_kernel<<<REC_CTAS, 256, REC_SMEM>>>(gate, p, A, state);

    // out = state @ Wo^T + bo
    mma_gemm<<<gg, 256>>>(state, Wo, nullptr, nullptr, bo, (float*)d_out,
                          nullptr, nullptr, 0, 0);
}

// round 10
// speedup vs baseline: 1.5461x; 1.0564x over previous
#include <cuda_runtime.h>
#include <cuda_bf16.h>
#include <math.h>
#include <stdint.h>

#define BATCH 4
#define SEQ   2048
#define DIM   1024
#define NCHUNK 16
#define CHUNK  128          // SEQ / NCHUNK
#define MROWS  (BATCH * SEQ)   // 8192

// ---------------- scratch (static device globals; no allocation) ----------------
__device__ float g_ret  [(size_t)MROWS * DIM];
__device__ float g_inp  [(size_t)MROWS * DIM];
__device__ float g_gate [(size_t)MROWS * DIM];
__device__ float g_u    [(size_t)MROWS * DIM];
__device__ float g_p    [(size_t)MROWS * DIM];
__device__ float g_state[(size_t)MROWS * DIM];
__device__ float g_y    [(size_t)MROWS * DIM];   // y_t = gate_{t+1} * state_t

#define REC_CTAS 128
#define REC_COLS 8
#define FLAG_STRIDE 8
__device__ unsigned int g_flags[REC_CTAS * FLAG_STRIDE];

__device__ float g_E   [BATCH * NCHUNK * DIM];
__device__ float g_cin [BATCH * NCHUNK * DIM];

// ---------------- helpers ----------------
__device__ __forceinline__ uint32_t smem_u32(const void* p) {
    uint32_t a;
    asm("{ .reg .u64 t; cvta.to.shared.u64 t, %1; cvt.u32.u64 %0, t; }"
        : "=r"(a) : "l"(p));
    return a;
}
__device__ __forceinline__ void ldm4(uint32_t* r, uint32_t addr) {
    asm volatile("ldmatrix.sync.aligned.m8n8.x4.shared.b16 {%0,%1,%2,%3}, [%4];"
                 : "=r"(r[0]), "=r"(r[1]), "=r"(r[2]), "=r"(r[3]) : "r"(addr));
}
__device__ __forceinline__ void mma16816(float* d, const uint32_t* a, const uint32_t* b) {
    asm volatile("mma.sync.aligned.m16n8k16.row.col.f32.bf16.bf16.f32 "
                 "{%0,%1,%2,%3}, {%4,%5,%6,%7}, {%8,%9}, {%0,%1,%2,%3};"
                 : "+f"(d[0]), "+f"(d[1]), "+f"(d[2]), "+f"(d[3])
                 : "r"(a[0]), "r"(a[1]), "r"(a[2]), "r"(a[3]),
                   "r"(b[0]), "r"(b[1]));
}

// ---------------- retention scan ----------------
__global__ void scan_pass1(const float* __restrict__ K, const float* __restrict__ V,
                           const float* __restrict__ decay)
{
    int d = blockIdx.x * 256 + threadIdx.x;
    int c = blockIdx.y;
    int b = blockIdx.z;
    float dec = decay[d >> 6];
    size_t base = ((size_t)b * SEQ + (size_t)c * CHUNK) * DIM + d;
    const float* kp = K + base;
    const float* vp = V + base;
    float r = 0.f;
#pragma unroll 8
    for (int i = 0; i < CHUNK; ++i)
        r = dec * r + kp[(size_t)i * DIM] * vp[(size_t)i * DIM];
    g_E[((size_t)b * NCHUNK + c) * DIM + d] = r;
}

__global__ void scan_pass2(const float* __restrict__ decay)
{
    int d = blockIdx.x * 256 + threadIdx.x;
    int b = blockIdx.y;
    float dec = decay[d >> 6];
    float decC = 1.f;
#pragma unroll
    for (int i = 0; i < CHUNK; ++i) decC *= dec;
    float carry = 0.f;
#pragma unroll
    for (int c = 0; c < NCHUNK; ++c) {
        size_t idx = ((size_t)b * NCHUNK + c) * DIM + d;
        g_cin[idx] = carry;
        carry = carry * decC + g_E[idx];
    }
}

__global__ void scan_pass3(const float* __restrict__ Q, const float* __restrict__ K,
                           const float* __restrict__ V, const float* __restrict__ decay)
{
    int d = blockIdx.x * 256 + threadIdx.x;
    int c = blockIdx.y;
    int b = blockIdx.z;
    float dec = decay[d >> 6];
    size_t base = ((size_t)b * SEQ + (size_t)c * CHUNK) * DIM + d;
    const float* qp = Q + base;
    const float* kp = K + base;
    const float* vp = V + base;
    float* rp = g_ret + base;
    float r = g_cin[((size_t)b * NCHUNK + c) * DIM + d];
#pragma unroll 8
    for (int i = 0; i < CHUNK; ++i) {
        r = dec * r + kp[(size_t)i * DIM] * vp[(size_t)i * DIM];
        rp[(size_t)i * DIM] = qp[(size_t)i * DIM] * r;
    }
}

// ================= pipelined mma.sync split-bf16 GEMM =================
// C[m,n] = sum_k X[m,k] * W[n,k]  (+ optional X2,W2 accumulated on top)
// D = Xhi*Whi + Xhi*Wlo + Xlo*Whi, fp32 register accumulators.
// Tile 128x128/CTA, BK=32, 8 warps (4m x 2n), warp tile 32x64.
// Double-buffered dynamic SMEM, 1 barrier per chunk:
//   iter c: LDG+cvt(c+1)->regs -> STS buf[(c+1)&1]; ldmatrix+MMA from buf[c&1]; bar.
#define GM_LDS    40                        // padded row elements: 80B stride
#define GM_TILE_B (128 * GM_LDS * 2)        // 10240 B per (tile,part)
#define GM_BUF_B  (4 * GM_TILE_B)           // Ahi|Alo|Bhi|Blo = 40960 B
#define GM_SMEM   (2 * GM_BUF_B)            // 81920 B

__device__ __forceinline__ void ld_cvt(uint32_t* r, const float* __restrict__ src,
                                       int rowBase, int kBase, int tid)
{
    const int row = tid >> 1;
    const int cb  = (tid & 1) * 16;
    const float4* sp = (const float4*)(src + (size_t)(rowBase + row) * DIM + kBase + cb);
#pragma unroll
    for (int j = 0; j < 4; ++j) {
        float4 v = sp[j];
        uint32_t u0 = __float_as_uint(v.x), u1 = __float_as_uint(v.y);
        uint32_t u2 = __float_as_uint(v.z), u3 = __float_as_uint(v.w);
        r[j*4+0] = (u0 >> 16) | (u1 & 0xFFFF0000u);
        r[j*4+1] = (u2 >> 16) | (u3 & 0xFFFF0000u);
        float l0 = v.x - __uint_as_float(u0 & 0xFFFF0000u);
        float l1 = v.y - __uint_as_float(u1 & 0xFFFF0000u);
        float l2 = v.z - __uint_as_float(u2 & 0xFFFF0000u);
        float l3 = v.w - __uint_as_float(u3 & 0xFFFF0000u);
        asm("cvt.rn.satfinite.bf16x2.f32 %0, %1, %2;" : "=r"(r[j*4+2]) : "f"(l1), "f"(l0));
        asm("cvt.rn.satfinite.bf16x2.f32 %0, %1, %2;" : "=r"(r[j*4+3]) : "f"(l3), "f"(l2));
    }
}

__device__ __forceinline__ void sts_tile(char* hiT, char* loT, const uint32_t* r, int tid)
{
    const int row = tid >> 1;
    const int cb  = (tid & 1) * 16;
#pragma unroll
    for (int j = 0; j < 4; ++j) {
        int bo = 2 * (row * GM_LDS + cb + j * 4);
        *(uint32_t*)(hiT + bo)     = r[j*4+0];
        *(uint32_t*)(hiT + bo + 4) = r[j*4+1];
        *(uint32_t*)(loT + bo)     = r[j*4+2];
        *(uint32_t*)(loT + bo + 4) = r[j*4+3];
    }
}

__global__ __launch_bounds__(256)
void mma_gemm(const float* __restrict__ X1, const float* __restrict__ W1,
              const float* __restrict__ X2, const float* __restrict__ W2,
              const float* __restrict__ bias, float* __restrict__ C,
              const float* __restrict__ auxIn, float* __restrict__ auxOut,
              int mode, int dual)
{
    extern __shared__ char dyn[];
    const uint32_t sb = smem_u32(dyn);
    const int tid = threadIdx.x;
    const int wid = tid >> 5, lane = tid & 31;
    const int wm = wid >> 1;            // 0..3: 32-row band
    const int wn = wid & 1;             // 0..1: 64-col band
    const int nTile = blockIdx.x * 128;
    const int mTile = blockIdx.y * 128;

    float acc[2][8][4];
#pragma unroll
    for (int mt = 0; mt < 2; ++mt)
#pragma unroll
        for (int nt = 0; nt < 8; ++nt)
#pragma unroll
            for (int r = 0; r < 4; ++r) acc[mt][nt][r] = 0.f;

    const uint32_t aRow  = wm * 32 + (lane & 15);
    const uint32_t aKoff = (lane >> 4) * 8;
    const uint32_t bRow  = wn * 64 + (lane & 7) + ((lane >> 4) << 3);
    const uint32_t bKoff = ((lane >> 3) & 1) * 8;

    uint32_t rA[16], rB[16];

    // prologue: chunk 0 -> buf0
    ld_cvt(rA, X1, mTile, 0, tid);
    ld_cvt(rB, W1, nTile, 0, tid);
    sts_tile(dyn, dyn + GM_TILE_B, rA, tid);
    sts_tile(dyn + 2 * GM_TILE_B, dyn + 3 * GM_TILE_B, rB, tid);
    __syncthreads();

    const int nCh = dual ? 64 : 32;
    for (int c = 0; c < nCh; ++c) {
        const int buf = c & 1;

        // prefetch chunk c+1 into the other buffer (regs die at STS)
        if (c + 1 < nCh) {
            const int c1 = c + 1;
            const float* X = (c1 >= 32) ? X2 : X1;
            const float* W = (c1 >= 32) ? W2 : W1;
            const int kB = (c1 & 31) * 32;
            ld_cvt(rA, X, mTile, kB, tid);
            ld_cvt(rB, W, nTile, kB, tid);
            char* nb = dyn + (buf ^ 1) * GM_BUF_B;
            sts_tile(nb, nb + GM_TILE_B, rA, tid);
            sts_tile(nb + 2 * GM_TILE_B, nb + 3 * GM_TILE_B, rB, tid);
        }

        // MMA on current buffer
        const uint32_t base = sb + buf * GM_BUF_B;
#pragma unroll
        for (int kk = 0; kk < 2; ++kk) {
            uint32_t ahi[2][4], alo[2][4];
#pragma unroll
            for (int mt = 0; mt < 2; ++mt) {
                uint32_t off = 2u * ((aRow + mt * 16) * GM_LDS + kk * 16 + aKoff);
                ldm4(ahi[mt], base + off);
                ldm4(alo[mt], base + GM_TILE_B + off);
            }
#pragma unroll
            for (int ng = 0; ng < 4; ++ng) {
                uint32_t bhi[4], blo[4];
                uint32_t off = 2u * ((bRow + ng * 16) * GM_LDS + kk * 16 + bKoff);
                ldm4(bhi, base + 2 * GM_TILE_B + off);
                ldm4(blo, base + 3 * GM_TILE_B + off);
#pragma unroll
                for (int mt = 0; mt < 2; ++mt)
#pragma unroll
                    for (int h = 0; h < 2; ++h) {
                        float* d = acc[mt][ng * 2 + h];
                        mma16816(d, ahi[mt], bhi + h * 2);
                        mma16816(d, ahi[mt], blo + h * 2);
                        mma16816(d, alo[mt], bhi + h * 2);
                    }
            }
        }
        __syncthreads();
    }

    // ---- epilogue from register accumulators ----
    const int g = lane >> 2, tig = lane & 3;
#pragma unroll
    for (int mt = 0; mt < 2; ++mt) {
#pragma unroll
        for (int nt = 0; nt < 8; ++nt) {
            const int col = nTile + wn * 64 + nt * 8 + tig * 2;
            const int r0 = mTile + wm * 32 + mt * 16 + g;
            const int r1 = r0 + 8;
            float* d = acc[mt][nt];
            if (mode == 0) {
                float2 bv = *(const float2*)(bias + col);
                *(float2*)(C + (size_t)r0 * DIM + col) =
                    make_float2(d[0] + bv.x, d[1] + bv.y);
                *(float2*)(C + (size_t)r1 * DIM + col) =
                    make_float2(d[2] + bv.x, d[3] + bv.y);
            } else if (mode == 1) {
                float2 bv = *(const float2*)(bias + col);
                float2 i0 = *(const float2*)(auxIn + (size_t)r0 * DIM + col);
                float2 i1 = *(const float2*)(auxIn + (size_t)r1 * DIM + col);
                float g0 = 1.f / (1.f + __expf(-(d[0] + bv.x)));
                float g1 = 1.f / (1.f + __expf(-(d[1] + bv.y)));
                float g2 = 1.f / (1.f + __expf(-(d[2] + bv.x)));
                float g3 = 1.f / (1.f + __expf(-(d[3] + bv.y)));
                *(float2*)(C + (size_t)r0 * DIM + col) = make_float2(g0, g1);
                *(float2*)(C + (size_t)r1 * DIM + col) = make_float2(g2, g3);
                *(float2*)(auxOut + (size_t)r0 * DIM + col) =
                    make_float2((1.f - g0) * i0.x, (1.f - g1) * i0.y);
                *(float2*)(auxOut + (size_t)r1 * DIM + col) =
                    make_float2((1.f - g2) * i1.x, (1.f - g3) * i1.y);
            } else {
                *(float2*)(C + (size_t)r0 * DIM + col) = make_float2(d[0], d[1]);
                *(float2*)(C + (size_t)r1 * DIM + col) = make_float2(d[2], d[3]);
            }
        }
    }
}

// ================= persistent state recurrence (v5 — proven) =================
#define REC_SMEM ((REC_COLS * DIM + BATCH * DIM + 8 * 16) * 4)

__global__ __launch_bounds__(256, 1)
void recurrence_kernel(const float* __restrict__ gate, const float* __restrict__ P,
                       const float* __restrict__ Amat, float* __restrict__ state)
{
    extern __shared__ float sh[];
    float* Asub = sh;
    float* xs   = sh + REC_COLS * DIM;
    float* red  = xs + BATCH * DIM;

    const int tid = threadIdx.x;
    const int warp = tid >> 5, lane = tid & 31;
    const int col0 = blockIdx.x * REC_COLS;
    const int cg = warp & 1;
    const int ks = warp >> 1;

    for (int i = tid; i < REC_COLS * DIM / 4; i += 256) {
        int c = i >> 8, k4 = i & 255;
        ((float4*)(Asub + c * DIM))[k4] =
            ((const float4*)(Amat + (size_t)(col0 + c) * DIM))[k4];
    }

    const int f_cg = tid >> 4, f_bb = (tid >> 2) & 3, f_c = tid & 3;
    const int f_col = col0 + f_cg * 4 + f_c;

    int pbb[4], pk4[4];
#pragma unroll
    for (int j = 0; j < 4; ++j) {
        int idx = tid + j * 256;
        pbb[j] = idx >> 8;
        pk4[j] = idx & 255;
    }

    __syncthreads();

    for (int t = 0; t < SEQ; ++t) {
        float pval = 0.f, gval = 0.f;
        if (tid < 32) {
            pval = P[((size_t)f_bb * SEQ + t) * DIM + f_col];
            if (t + 1 < SEQ)
                gval = gate[((size_t)f_bb * SEQ + (t + 1)) * DIM + f_col];
        }

        if (t > 0 && warp == 0) {
            unsigned tgt = (unsigned)t;
            bool ok;
            do {
                bool good = true;
#pragma unroll
                for (int j = 0; j < 4; ++j) {
                    unsigned f = *(volatile const unsigned*)
                        &g_flags[(lane + 32 * j) * FLAG_STRIDE];
                    good = good && (f >= tgt);
                }
                ok = __all_sync(0xffffffffu, good);
            } while (!ok);
        }
        __syncthreads();

        if (t == 0) {
#pragma unroll
            for (int j = 0; j < 4; ++j)
                ((float4*)(xs + pbb[j] * DIM))[pk4[j]] = make_float4(0.f, 0.f, 0.f, 0.f);
        } else {
#pragma unroll
            for (int j = 0; j < 4; ++j) {
                float4 y4 = __ldcg(&((const float4*)(g_y + ((size_t)pbb[j] * SEQ + t - 1) * DIM))[pk4[j]]);
                ((float4*)(xs + pbb[j] * DIM))[pk4[j]] = y4;
            }
        }
        __syncthreads();

        float acc[4][4];
#pragma unroll
        for (int bb = 0; bb < 4; ++bb)
#pragma unroll
            for (int c = 0; c < 4; ++c) acc[bb][c] = 0.f;

#pragma unroll
        for (int i = 0; i < 2; ++i) {
            int k4 = ks * 64 + i * 32 + lane;
            float4 x4[4];
#pragma unroll
            for (int bb = 0; bb < 4; ++bb)
                x4[bb] = ((const float4*)(xs + bb * DIM))[k4];
#pragma unroll
            for (int c = 0; c < 4; ++c) {
                float4 a4 = ((const float4*)(Asub + (cg * 4 + c) * DIM))[k4];
#pragma unroll
                for (int bb = 0; bb < 4; ++bb) {
                    acc[bb][c] += x4[bb].x * a4.x + x4[bb].y * a4.y +
                                  x4[bb].z * a4.z + x4[bb].w * a4.w;
                }
            }
        }
#pragma unroll
        for (int bb = 0; bb < 4; ++bb)
#pragma unroll
            for (int c = 0; c < 4; ++c) {
                float v = acc[bb][c];
#pragma unroll
                for (int off = 16; off; off >>= 1)
                    v += __shfl_xor_sync(0xffffffffu, v, off);
                acc[bb][c] = v;
            }
        if (lane == 0) {
#pragma unroll
            for (int bb = 0; bb < 4; ++bb)
#pragma unroll
                for (int c = 0; c < 4; ++c)
                    red[warp * 16 + bb * 4 + c] = acc[bb][c];
        }
        __syncthreads();

        if (tid < 32) {
            float s = 0.f;
#pragma unroll
            for (int k = 0; k < 4; ++k)
                s += red[(k * 2 + f_cg) * 16 + f_bb * 4 + f_c];
            float sv = tanhf(s + pval);
            size_t idx = ((size_t)f_bb * SEQ + t) * DIM + f_col;
            __stcg(&state[idx], sv);
            if (t + 1 < SEQ)
                __stcg(&g_y[idx], sv * gval);
            __threadfence();
        }
        __syncthreads();

        if (tid == 0)
            *(volatile unsigned*)&g_flags[blockIdx.x * FLAG_STRIDE] = (unsigned)(t + 1);
        __syncthreads();
    }
}

__global__ void reset_flags()
{
    int i = threadIdx.x;
    if (i < REC_CTAS * FLAG_STRIDE) g_flags[i] = 0u;
}

// ================= launch =================
extern "C" void kernel_launch(void* const* d_in, const int* in_sizes, int n_in,
                              void* d_out, int out_size)
{
    const float* q     = (const float*)d_in[0];
    const float* k     = (const float*)d_in[1];
    const float* v     = (const float*)d_in[2];
    const float* Wi    = (const float*)d_in[3];
    const float* bi    = (const float*)d_in[4];
    const float* Wg    = (const float*)d_in[5];
    const float* bg    = (const float*)d_in[6];
    const float* A     = (const float*)d_in[7];
    const float* Bm    = (const float*)d_in[8];
    const float* Wo    = (const float*)d_in[9];
    const float* bo    = (const float*)d_in[10];
    const float* decay = (const float*)d_in[11];

    float *ret, *inp, *gate, *u, *p, *state;
    cudaGetSymbolAddress((void**)&ret,   g_ret);
    cudaGetSymbolAddress((void**)&inp,   g_inp);
    cudaGetSymbolAddress((void**)&gate,  g_gate);
    cudaGetSymbolAddress((void**)&u,     g_u);
    cudaGetSymbolAddress((void**)&p,     g_p);
    cudaGetSymbolAddress((void**)&state, g_state);

    cudaFuncSetAttribute(recurrence_kernel,
                         cudaFuncAttributeMaxDynamicSharedMemorySize, REC_SMEM);
    cudaFuncSetAttribute(mma_gemm,
                         cudaFuncAttributeMaxDynamicSharedMemorySize, GM_SMEM);

    dim3 sg(DIM / 256, NCHUNK, BATCH);
    scan_pass1<<<sg, 256>>>(k, v, decay);
    scan_pass2<<<dim3(DIM / 256, BATCH), 256>>>(decay);
    scan_pass3<<<sg, 256>>>(q, k, v, decay);

    dim3 gg(DIM / 128, MROWS / 128);   // (8, 64)
    // inp = ret @ Wi^T + bi
    mma_gemm<<<gg, 256, GM_SMEM>>>(ret, Wi, nullptr, nullptr, bi, inp,
                                   nullptr, nullptr, 0, 0);
    // gate = sigmoid(inp @ Wg^T + bg); u = (1-gate) * inp
    mma_gemm<<<gg, 256, GM_SMEM>>>(inp, Wg, nullptr, nullptr, bg, gate,
                                   inp, u, 1, 0);
    // p = u @ A^T + inp @ Bm^T   (fused dual accumulation)
    mma_gemm<<<gg, 256, GM_SMEM>>>(u, A, inp, Bm, nullptr, p,
                                   nullptr, nullptr, 3, 1);

    reset_flags<<<1, 1024>>>();
    recurrence_kernel<<<REC_CTAS, 256, REC_SMEM>>>(gate, p, A, state);

    // out = state @ Wo^T + bo
    mma_gemm<<<gg, 256, GM_SMEM>>>(state, Wo, nullptr, nullptr, bo, (float*)d_out,
                                   nullptr, nullptr, 0, 0);
}